// round 10
// baseline (speedup 1.0000x reference)
#include <cuda_runtime.h>
#include <stdint.h>

#define NN 8192
#define DDIM 128
#define WPR 256                    // 8192 bits / 32 words per row
#define MAXNNZ 128
#define NTHR 256

// -------- persistent scratch (no allocations allowed) --------
__device__ __align__(16) uint32_t g_mask[NN * WPR];   // 8 MB adjacency bitmask (edges only, no eye)
__device__ __align__(16) int      g_deg[NN];          // dedup'd edge degree (no eye)
__device__ __align__(16) float    g_ys[NN * DDIM];    // ys[j] = d_j^{-1/2} * (x @ W^T)[j]
__device__ int      g_is64;                           // edge_index dtype flag
__device__ unsigned g_barcnt;                         // monotone grid-barrier counter (replay-safe)

// Grid-wide barrier: all G blocks co-resident (guaranteed by occupancy-sized launch).
// Counter never resets; barriers are totally ordered, so target = next multiple of G.
__device__ __forceinline__ void grid_barrier(unsigned G) {
    __syncthreads();
    if (threadIdx.x == 0) {
        __threadfence();                               // release my writes
        unsigned old = atomicAdd(&g_barcnt, 1u);
        unsigned tgt = (old / G + 1u) * G;
        while (*(volatile unsigned*)&g_barcnt < tgt) __nanosleep(32);
    }
    __syncthreads();
}

__global__ void __launch_bounds__(NTHR)
k_fused(const float* __restrict__ x, const void* __restrict__ eiraw,
        const float* __restrict__ W, const float* __restrict__ bias,
        float* __restrict__ out, int E, unsigned G) {
    // NOTE: 'part' must be 16B-aligned (float4 STS/LDS) -> it is FIRST member, union aligned.
    __shared__ __align__(16) union {
        struct { float sW[64 * 129]; float sx[32 * 64]; } g;                  // gemm (41KB)
        struct { float part[8][128]; int sj[MAXNNZ + 1]; int wsum[8]; } a;    // aggregate
    } sh;

    const int t    = threadIdx.x;
    const int lane = t & 31;
    const int w    = t >> 5;
    const unsigned gtid = blockIdx.x * NTHR + t;
    const unsigned gstride = G * NTHR;

    // ---- Phase 1: zero mask+deg; block 0 detects int64 vs int32 edge_index ----
    // (indices < 8192 -> for int64 every odd 32-bit word is 0; P(false positive) ~ 8192^-128)
    if (blockIdx.x == 0) {
        const uint32_t* raw = (const uint32_t*)eiraw;
        int nz = (t < 128) ? (raw[2 * t + 1] != 0u) : 0;
        int any = __syncthreads_or(nz);
        if (t == 0) g_is64 = !any;
    }
    {
        const uint4 z = make_uint4(0u, 0u, 0u, 0u);
        uint4* pm = reinterpret_cast<uint4*>(g_mask);
        for (unsigned i = gtid; i < NN * WPR / 4; i += gstride) pm[i] = z;
        uint4* pd = reinterpret_cast<uint4*>(g_deg);
        for (unsigned i = gtid; i < NN / 4; i += gstride) pd[i] = z;
    }
    grid_barrier(G);

    // ---- Phase 2: scatter edges; atomicOr old-value gives exact dedup'd degree ----
    {
        int is64 = g_is64;
        for (int e = gtid; e < E; e += gstride) {
            int r, c;
            if (is64) {
                const long long* ei = (const long long*)eiraw;
                r = (int)ei[e]; c = (int)ei[E + e];
            } else {
                const int* ei = (const int*)eiraw;
                r = ei[e]; c = ei[E + e];
            }
            r &= (NN - 1); c &= (NN - 1);
            uint32_t bit = 1u << (c & 31);
            uint32_t old = atomicOr(&g_mask[r * WPR + (c >> 5)], bit);
            if (!(old & bit)) atomicAdd(&g_deg[r], 1);
        }
    }
    grid_barrier(G);

    // ---- Phase 3: ys = diag(d^-1/2) * (x @ W^T), 32-row tiles, 256 threads ----
    {
        const int tx = lane;           // feature lane: features tx + 32q
        const int ty = w;              // row group 0..7: rows r0 + ty + 8p
        for (int tile = blockIdx.x; tile < NN / 32; tile += G) {
            int r0 = tile * 32;
            float acc[4][4];
            #pragma unroll
            for (int q = 0; q < 4; q++)
                #pragma unroll
                for (int p = 0; p < 4; p++) acc[q][p] = 0.f;
            for (int ch = 0; ch < 2; ch++) {
                __syncthreads();
                for (int i = t; i < 128 * 64; i += NTHR) {      // sW[k][f] = W[f][ch*64+k]
                    int f = i >> 6, k = i & 63;
                    sh.g.sW[k * 129 + f] = W[f * 128 + ch * 64 + k];
                }
                for (int i = t; i < 32 * 64; i += NTHR) {       // sx[r][k] = x[r0+r][ch*64+k]
                    int r = i >> 6, k = i & 63;
                    sh.g.sx[r * 64 + k] = x[(r0 + r) * 128 + ch * 64 + k];
                }
                __syncthreads();
                #pragma unroll 8
                for (int k = 0; k < 64; k++) {
                    float wv[4];
                    #pragma unroll
                    for (int q = 0; q < 4; q++) wv[q] = sh.g.sW[k * 129 + tx + 32 * q];
                    #pragma unroll
                    for (int p = 0; p < 4; p++) {
                        float xv = sh.g.sx[(ty + 8 * p) * 64 + k];
                        #pragma unroll
                        for (int q = 0; q < 4; q++) acc[q][p] += xv * wv[q];
                    }
                }
            }
            #pragma unroll
            for (int p = 0; p < 4; p++) {
                int r = r0 + ty + 8 * p;
                float d = rsqrtf((float)__ldcg(&g_deg[r]) + 1.0f);   // +eye in degree
                #pragma unroll
                for (int q = 0; q < 4; q++)
                    g_ys[r * 128 + tx + 32 * q] = d * acc[q][p];
            }
            __syncthreads();
        }
    }
    grid_barrier(G);

    // ---- Phase 4: extract + aggregate. One row per block-iteration; 8 warp gather streams.
    // out[i] = d_i^{-1/2} * (sum_{j in row} ys[j] + ys[i]) + b   (self appended = +eye;
    // a self-edge bit also in the list makes the diagonal 2, matching the reference).
    for (int i = blockIdx.x; i < NN; i += G) {
        __syncthreads();                                    // smem reuse guard
        uint32_t word = __ldcg(&g_mask[i * WPR + t]);       // 1 word per thread, coalesced
        int cnt = __popc(word);
        int pre = cnt;                                      // warp-inclusive scan
        #pragma unroll
        for (int o = 1; o < 32; o <<= 1) {
            int v = __shfl_up_sync(0xFFFFFFFFu, pre, o);
            if (lane >= o) pre += v;
        }
        if (lane == 31) sh.a.wsum[w] = pre;
        __syncthreads();
        int base = 0, nn = 0;
        #pragma unroll
        for (int q = 0; q < 8; q++) {
            int s = sh.a.wsum[q];
            base += (q < w) ? s : 0;
            nn += s;
        }
        int pos = base + (pre - cnt);                       // exclusive position
        while (word) {
            int b = __ffs(word) - 1; word &= word - 1;
            if (pos < MAXNNZ) sh.a.sj[pos] = t * 32 + b;
            pos++;
        }
        if (nn > MAXNNZ) nn = MAXNNZ;
        if (t == 0) sh.a.sj[nn] = i;                        // +eye: self row once
        int nn1 = nn + 1;
        __syncthreads();

        float4 acc = make_float4(0.f, 0.f, 0.f, 0.f);
        #pragma unroll 2
        for (int n = w; n < nn1; n += 8) {
            int j = sh.a.sj[n];
            float4 v = *reinterpret_cast<const float4*>(&g_ys[j * 128 + lane * 4]);
            acc.x += v.x; acc.y += v.y; acc.z += v.z; acc.w += v.w;
        }
        reinterpret_cast<float4*>(sh.a.part[w])[lane] = acc;
        __syncthreads();
        if (t < 128) {
            float r = 0.f;
            #pragma unroll
            for (int q = 0; q < 8; q++) r += sh.a.part[q][t];
            float di = rsqrtf((float)__ldcg(&g_deg[i]) + 1.0f);
            out[i * 128 + t] = di * r + bias[t];
        }
    }
}

extern "C" void kernel_launch(void* const* d_in, const int* in_sizes, int n_in,
                              void* d_out, int out_size) {
    const float* x  = (const float*)d_in[0];
    const void*  ei = d_in[1];
    const float* W  = (const float*)d_in[2];
    const float* b  = (const float*)d_in[3];
    float* out = (float*)d_out;
    int E = in_sizes[1] / 2;

    int dev = 0, numSM = 0, maxB = 0;
    cudaGetDevice(&dev);
    cudaDeviceGetAttribute(&numSM, cudaDevAttrMultiProcessorCount, dev);
    cudaOccupancyMaxActiveBlocksPerMultiprocessor(&maxB, k_fused, NTHR, 0);
    if (maxB < 1) maxB = 1;
    unsigned G = (unsigned)(numSM * maxB);    // all blocks co-resident -> barrier is safe

    k_fused<<<G, NTHR>>>(x, ei, W, b, out, E, G);
}

// round 11
// speedup vs baseline: 1.4274x; 1.4274x over previous
#include <cuda_runtime.h>
#include <stdint.h>

#define NN 8192
#define WPR 256                    // 8192 bits / 32 words per row
#define MAXNNZ 128

// -------- scratch (no allocations allowed) --------
__device__ __align__(16) uint32_t g_mask[NN * WPR];   // 8 MB adjacency bitmask (edges only, no eye)
__device__ __align__(16) int      g_deg[NN];          // dedup'd edge degree (no eye)
__device__ __align__(16) float    g_ys[NN * 128];     // ys[j] = d_j^{-1/2} * (x @ W^T)[j]
__device__ int g_is64;                                // edge_index dtype flag (auto-detected)

// K1: zero mask + deg; block 0 also detects int64 vs int32 edge_index
// (values < 8192 -> for int64 every odd 32-bit word is 0; P(false positive) ~ 8192^-128).
__global__ void k_zero(const uint32_t* __restrict__ raw) {
    if (blockIdx.x == 0) {
        int t = threadIdx.x;
        int nz = (t < 128) ? (raw[2 * t + 1] != 0u) : 0;
        int any = __syncthreads_or(nz);
        if (t == 0) g_is64 = !any;
    }
    const uint4 z = make_uint4(0u, 0u, 0u, 0u);
    int tid = blockIdx.x * blockDim.x + threadIdx.x;
    int stride = gridDim.x * blockDim.x;
    uint4* pm = reinterpret_cast<uint4*>(g_mask);
    for (int i = tid; i < NN * WPR / 4; i += stride) pm[i] = z;
    uint4* pd = reinterpret_cast<uint4*>(g_deg);
    for (int i = tid; i < NN / 4; i += stride) pd[i] = z;
}

// K2: scatter edges; atomicOr's OLD value identifies the unique setter of each bit
// -> exact dedup'd degree via atomicAdd (addresses spread across 8192 rows).
__global__ void k_scatter(const void* __restrict__ eiraw, int E) {
    int e = blockIdx.x * blockDim.x + threadIdx.x;
    if (e >= E) return;
    int r, c;
    if (g_is64) {
        const long long* ei = (const long long*)eiraw;
        r = (int)ei[e];
        c = (int)ei[E + e];
    } else {
        const int* ei = (const int*)eiraw;
        r = ei[e];
        c = ei[E + e];
    }
    r &= (NN - 1);
    c &= (NN - 1);
    uint32_t bit = 1u << (c & 31);
    uint32_t old = atomicOr(&g_mask[r * WPR + (c >> 5)], bit);
    if (!(old & bit)) atomicAdd(&g_deg[r], 1);
}

// K3: ys = diag(d^{-1/2}) * (x @ W^T).  M=8192, N=128, K=128 fp32 (scalar FFMA tile, proven).
__global__ void k_gemm_xw(const float* __restrict__ x, const float* __restrict__ W) {
    __shared__ float sW[64 * 129];   // sW[k*129 + f] : conflict-free
    __shared__ float sx[32 * 64];    // sx[r*64 + k]  : broadcast reads
    int t  = threadIdx.x;
    int tx = t & 31;                 // feature lane
    int ty = t >> 5;                 // row group
    int r0 = blockIdx.x * 32;

    float acc[4][8];
    #pragma unroll
    for (int q = 0; q < 4; q++)
        #pragma unroll
        for (int p = 0; p < 8; p++) acc[q][p] = 0.f;

    for (int ch = 0; ch < 2; ch++) {
        __syncthreads();
        for (int i = t; i < 128 * 64; i += 128) {       // sW[k][f] = W[f][ch*64+k]
            int f = i >> 6, k = i & 63;
            sW[k * 129 + f] = W[f * 128 + ch * 64 + k];
        }
        for (int i = t; i < 32 * 64; i += 128) {        // sx[r][k] = x[r0+r][ch*64+k]
            int r = i >> 6, k = i & 63;
            sx[r * 64 + k] = x[(r0 + r) * 128 + ch * 64 + k];
        }
        __syncthreads();
        #pragma unroll 8
        for (int k = 0; k < 64; k++) {
            float wv[4];
            #pragma unroll
            for (int q = 0; q < 4; q++) wv[q] = sW[k * 129 + tx + 32 * q];
            #pragma unroll
            for (int p = 0; p < 8; p++) {
                float xv = sx[(ty + 4 * p) * 64 + k];
                #pragma unroll
                for (int q = 0; q < 4; q++) acc[q][p] += xv * wv[q];
            }
        }
    }
    #pragma unroll
    for (int p = 0; p < 8; p++) {
        int r = r0 + ty + 4 * p;
        float d = rsqrtf((float)g_deg[r] + 1.0f);       // +eye in degree
        #pragma unroll
        for (int q = 0; q < 4; q++)
            g_ys[r * 128 + tx + 32 * q] = d * acc[q][p];
    }
}

// K4: WARP-per-row extract + aggregate. 8 warps/block, no block barriers.
// Lane loads 8 mask words (coalesced: row[lane + 32k]); warp shfl-scan assigns compaction
// slots; extraction into a per-warp smem segment (__syncwarp only). Gather: each lane owns
// features [4*lane, 4*lane+4) and sums float4 over all neighbors in registers — no combine.
// out[i] = d_i^{-1/2} * (sum_{j in row i} ys[j] + ys[i]) + b   (self appended = +eye;
// a self-edge bit also in the list makes the diagonal 2, matching the reference).
__global__ void __launch_bounds__(256)
k_aggregate(const float* __restrict__ bias, float* __restrict__ out) {
    const int t    = threadIdx.x;
    const int lane = t & 31;
    const int w    = t >> 5;
    const int i    = blockIdx.x * 8 + w;     // row
    __shared__ int sj[8][MAXNNZ + 8];        // per-warp neighbor lists

    // 1) load 8 words per lane, coalesced within each k-step
    const uint32_t* row = g_mask + i * WPR;
    uint32_t wd[8];
    #pragma unroll
    for (int k = 0; k < 8; k++) wd[k] = row[lane + 32 * k];
    int cnt = 0;
    #pragma unroll
    for (int k = 0; k < 8; k++) cnt += __popc(wd[k]);

    // 2) warp-exclusive scan of cnt -> starting slot
    int pre = cnt;
    #pragma unroll
    for (int o = 1; o < 32; o <<= 1) {
        int v = __shfl_up_sync(0xFFFFFFFFu, pre, o);
        if (lane >= o) pre += v;
    }
    int nn  = __shfl_sync(0xFFFFFFFFu, pre, 31);   // warp total
    int pos = pre - cnt;

    // 3) emit bit indices into this warp's segment (order irrelevant: it's a sum)
    int* lst = sj[w];
    #pragma unroll
    for (int k = 0; k < 8; k++) {
        uint32_t word = wd[k];
        int base = (lane + 32 * k) * 32;
        while (word) {
            int b = __ffs(word) - 1; word &= word - 1;
            if (pos < MAXNNZ) lst[pos] = base + b;
            pos++;
        }
    }
    if (nn > MAXNNZ) nn = MAXNNZ;
    if (lane == 0) lst[nn] = i;                    // +eye: self row once
    int nn1 = nn + 1;
    __syncwarp();

    // 4) gather: lane sums its float4 feature chunk over all neighbors; 4-way MLP unroll
    float4 a0 = make_float4(0.f, 0.f, 0.f, 0.f);
    float4 a1 = make_float4(0.f, 0.f, 0.f, 0.f);
    int n = 0;
    for (; n + 4 <= nn1; n += 4) {
        int j0 = lst[n], j1 = lst[n + 1], j2 = lst[n + 2], j3 = lst[n + 3];
        float4 v0 = *reinterpret_cast<const float4*>(&g_ys[j0 * 128 + lane * 4]);
        float4 v1 = *reinterpret_cast<const float4*>(&g_ys[j1 * 128 + lane * 4]);
        float4 v2 = *reinterpret_cast<const float4*>(&g_ys[j2 * 128 + lane * 4]);
        float4 v3 = *reinterpret_cast<const float4*>(&g_ys[j3 * 128 + lane * 4]);
        a0.x += v0.x + v1.x; a0.y += v0.y + v1.y; a0.z += v0.z + v1.z; a0.w += v0.w + v1.w;
        a1.x += v2.x + v3.x; a1.y += v2.y + v3.y; a1.z += v2.z + v3.z; a1.w += v2.w + v3.w;
    }
    for (; n < nn1; n++) {
        int j = lst[n];
        float4 v = *reinterpret_cast<const float4*>(&g_ys[j * 128 + lane * 4]);
        a0.x += v.x; a0.y += v.y; a0.z += v.z; a0.w += v.w;
    }
    float di = rsqrtf((float)g_deg[i] + 1.0f);
    float4 bb = *reinterpret_cast<const float4*>(&bias[lane * 4]);
    float4 r;
    r.x = di * (a0.x + a1.x) + bb.x;
    r.y = di * (a0.y + a1.y) + bb.y;
    r.z = di * (a0.z + a1.z) + bb.z;
    r.w = di * (a0.w + a1.w) + bb.w;
    *reinterpret_cast<float4*>(&out[i * 128 + lane * 4]) = r;
}

extern "C" void kernel_launch(void* const* d_in, const int* in_sizes, int n_in,
                              void* d_out, int out_size) {
    const float* x  = (const float*)d_in[0];
    const void*  ei = d_in[1];
    const float* W  = (const float*)d_in[2];
    const float* b  = (const float*)d_in[3];
    float* out = (float*)d_out;
    int E = in_sizes[1] / 2;   // element count / 2, dtype-independent

    k_zero<<<512, 256>>>((const uint32_t*)ei);
    k_scatter<<<(E + 255) / 256, 256>>>(ei, E);
    k_gemm_xw<<<NN / 32, 128>>>(x, W);
    k_aggregate<<<NN / 8, 256>>>(b, out);
}

// round 13
// speedup vs baseline: 1.5491x; 1.0853x over previous
#include <cuda_runtime.h>
#include <stdint.h>

#define NN 8192
#define WPR 256                    // 8192 bits / 32 words per row
#define MAXNNZ 128

// -------- scratch (no allocations allowed) --------
// INVARIANT: g_mask and g_deg are all-zero at every kernel_launch entry.
// CUDA zero-initializes __device__ globals at load; k_aggregate restores zero each call.
__device__ __align__(16) uint32_t g_mask[NN * WPR];   // 8 MB adjacency bitmask (edges only, no eye)
__device__ __align__(16) int      g_deg[NN];          // dedup'd edge degree (no eye)
__device__ __align__(16) float    g_ys[NN * 128];     // ys[j] = d_j^{-1/2} * (x @ W^T)[j]

// K1: scatter edges; atomicOr's OLD value identifies the unique setter of each bit
// -> exact dedup'd degree via atomicAdd. Per-block dtype detect: indices < 8192, so for
// int64 every odd 32-bit word is 0 (P(false positive for int32) ~ 8192^-128).
__global__ void __launch_bounds__(256)
k_scatter(const void* __restrict__ eiraw, int E) {
    const uint32_t* raw = (const uint32_t*)eiraw;
    int nz = (threadIdx.x < 128) ? (raw[2 * threadIdx.x + 1] != 0u) : 0;
    int is64 = !__syncthreads_or(nz);

    int e = blockIdx.x * blockDim.x + threadIdx.x;
    if (e >= E) return;
    int r, c;
    if (is64) {
        const long long* ei = (const long long*)eiraw;
        r = (int)ei[e];
        c = (int)ei[E + e];
    } else {
        const int* ei = (const int*)eiraw;
        r = ei[e];
        c = ei[E + e];
    }
    r &= (NN - 1);
    c &= (NN - 1);
    uint32_t bit = 1u << (c & 31);
    uint32_t old = atomicOr(&g_mask[r * WPR + (c >> 5)], bit);
    if (!(old & bit)) atomicAdd(&g_deg[r], 1);
}

// K2: ys = diag(d^{-1/2}) * (x @ W^T).  M=8192, N=128, K=128 fp32 (scalar FFMA tile, proven).
__global__ void k_gemm_xw(const float* __restrict__ x, const float* __restrict__ W) {
    __shared__ float sW[64 * 129];   // sW[k*129 + f] : conflict-free
    __shared__ float sx[32 * 64];    // sx[r*64 + k]  : broadcast reads
    int t  = threadIdx.x;
    int tx = t & 31;                 // feature lane
    int ty = t >> 5;                 // row group
    int r0 = blockIdx.x * 32;

    float acc[4][8];
    #pragma unroll
    for (int q = 0; q < 4; q++)
        #pragma unroll
        for (int p = 0; p < 8; p++) acc[q][p] = 0.f;

    for (int ch = 0; ch < 2; ch++) {
        __syncthreads();
        for (int i = t; i < 128 * 64; i += 128) {       // sW[k][f] = W[f][ch*64+k]
            int f = i >> 6, k = i & 63;
            sW[k * 129 + f] = W[f * 128 + ch * 64 + k];
        }
        for (int i = t; i < 32 * 64; i += 128) {        // sx[r][k] = x[r0+r][ch*64+k]
            int r = i >> 6, k = i & 63;
            sx[r * 64 + k] = x[(r0 + r) * 128 + ch * 64 + k];
        }
        __syncthreads();
        #pragma unroll 8
        for (int k = 0; k < 64; k++) {
            float wv[4];
            #pragma unroll
            for (int q = 0; q < 4; q++) wv[q] = sW[k * 129 + tx + 32 * q];
            #pragma unroll
            for (int p = 0; p < 8; p++) {
                float xv = sx[(ty + 4 * p) * 64 + k];
                #pragma unroll
                for (int q = 0; q < 4; q++) acc[q][p] += xv * wv[q];
            }
        }
    }
    #pragma unroll
    for (int p = 0; p < 8; p++) {
        int r = r0 + ty + 4 * p;
        float d = rsqrtf((float)g_deg[r] + 1.0f);       // +eye in degree
        #pragma unroll
        for (int q = 0; q < 4; q++)
            g_ys[r * 128 + tx + 32 * q] = d * acc[q][p];
    }
}

// K3: WARP-per-row extract + aggregate + state reset. 8 warps/block, no block barriers.
// After extraction, the warp re-zeros its mask row and deg entry (restores the all-zero
// invariant for the next replay; stores retire under the gather latency).
// out[i] = d_i^{-1/2} * (sum_{j in row i} ys[j] + ys[i]) + b   (self appended = +eye;
// a self-edge bit also in the list makes the diagonal 2, matching the reference).
__global__ void __launch_bounds__(256, 8)
k_aggregate(const float* __restrict__ bias, float* __restrict__ out) {
    const int t    = threadIdx.x;
    const int lane = t & 31;
    const int w    = t >> 5;
    const int i    = blockIdx.x * 8 + w;     // row
    __shared__ int sj[8][MAXNNZ + 8];        // per-warp neighbor lists

    // 1) load 8 words per lane, coalesced within each k-step; read deg before reset
    uint32_t* row = g_mask + i * WPR;
    const int degi = g_deg[i];
    uint32_t wd[8];
    #pragma unroll
    for (int k = 0; k < 8; k++) wd[k] = row[lane + 32 * k];
    int cnt = 0;
    #pragma unroll
    for (int k = 0; k < 8; k++) cnt += __popc(wd[k]);

    // 2) warp-exclusive scan of cnt -> starting slot
    int pre = cnt;
    #pragma unroll
    for (int o = 1; o < 32; o <<= 1) {
        int v = __shfl_up_sync(0xFFFFFFFFu, pre, o);
        if (lane >= o) pre += v;
    }
    int nn  = __shfl_sync(0xFFFFFFFFu, pre, 31);   // warp total
    int pos = pre - cnt;

    // 3) emit bit indices into this warp's segment (order irrelevant: it's a sum)
    int* lst = sj[w];
    #pragma unroll
    for (int k = 0; k < 8; k++) {
        uint32_t word = wd[k];
        int base = (lane + 32 * k) * 32;
        while (word) {
            int b = __ffs(word) - 1; word &= word - 1;
            if (pos < MAXNNZ) lst[pos] = base + b;
            pos++;
        }
    }
    if (nn > MAXNNZ) nn = MAXNNZ;
    if (lane == 0) {
        lst[nn] = i;                               // +eye: self row once
        g_deg[i] = 0;                              // reset invariant
    }
    // reset this row's mask (same coalesced pattern as the loads; retires under gather)
    #pragma unroll
    for (int k = 0; k < 8; k++) row[lane + 32 * k] = 0u;
    int nn1 = nn + 1;
    __syncwarp();

    // 4) gather: lane sums its float4 feature chunk over all neighbors; 4-way MLP unroll
    float4 a0 = make_float4(0.f, 0.f, 0.f, 0.f);
    float4 a1 = make_float4(0.f, 0.f, 0.f, 0.f);
    int n = 0;
    for (; n + 4 <= nn1; n += 4) {
        int j0 = lst[n], j1 = lst[n + 1], j2 = lst[n + 2], j3 = lst[n + 3];
        float4 v0 = *reinterpret_cast<const float4*>(&g_ys[j0 * 128 + lane * 4]);
        float4 v1 = *reinterpret_cast<const float4*>(&g_ys[j1 * 128 + lane * 4]);
        float4 v2 = *reinterpret_cast<const float4*>(&g_ys[j2 * 128 + lane * 4]);
        float4 v3 = *reinterpret_cast<const float4*>(&g_ys[j3 * 128 + lane * 4]);
        a0.x += v0.x + v1.x; a0.y += v0.y + v1.y; a0.z += v0.z + v1.z; a0.w += v0.w + v1.w;
        a1.x += v2.x + v3.x; a1.y += v2.y + v3.y; a1.z += v2.z + v3.z; a1.w += v2.w + v3.w;
    }
    for (; n < nn1; n++) {
        int j = lst[n];
        float4 v = *reinterpret_cast<const float4*>(&g_ys[j * 128 + lane * 4]);
        a0.x += v.x; a0.y += v.y; a0.z += v.z; a0.w += v.w;
    }
    float di = rsqrtf((float)degi + 1.0f);
    float4 bb = *reinterpret_cast<const float4*>(&bias[lane * 4]);
    float4 r;
    r.x = di * (a0.x + a1.x) + bb.x;
    r.y = di * (a0.y + a1.y) + bb.y;
    r.z = di * (a0.z + a1.z) + bb.z;
    r.w = di * (a0.w + a1.w) + bb.w;
    *reinterpret_cast<float4*>(&out[i * 128 + lane * 4]) = r;
}

extern "C" void kernel_launch(void* const* d_in, const int* in_sizes, int n_in,
                              void* d_out, int out_size) {
    const float* x  = (const float*)d_in[0];
    const void*  ei = d_in[1];
    const float* W  = (const float*)d_in[2];
    const float* b  = (const float*)d_in[3];
    float* out = (float*)d_out;
    int E = in_sizes[1] / 2;   // element count / 2, dtype-independent

    k_scatter<<<(E + 255) / 256, 256>>>(ei, E);
    k_gemm_xw<<<NN / 32, 128>>>(x, W);
    k_aggregate<<<NN / 8, 256>>>(b, out);
}